// round 14
// baseline (speedup 1.0000x reference)
#include <cuda_runtime.h>
#include <cuda_bf16.h>
#include <cuda_fp16.h>
#include <cstdint>

// ---------------------------------------------------------------------------
// RelationLayer: L=128, B=16, E=512, C=64, KERNELS={1,3,5,7}, M=256, OUT=256
//  1) prep: conv weights -> fp16, Wuv -> fp16, pair W2 fragments packed
//  2) G = x(2048x512) @ Wr    (fp16 GEMM, x converted inline, G stored fp16)
//  3) guv: gather taps -> f (smem fp16) -> uv = f @ Wuv, fused single kernel
//  4) pair kernel: round-6 structure, pure fp16 MMA, W2 loaded pre-packed.
// ---------------------------------------------------------------------------

#define LL 128
#define BB 16
#define EE 512
#define MM 256
#define ROWS 2048
#define GCOLS 1024

#define NW (EE * GCOLS)
#define NU (128 * MM)

__device__ __half g_Gh[ROWS * GCOLS];
__device__ float g_uv[ROWS * 128];
__device__ __half g_Wrh[NW];
__device__ __half g_Wuvh[NU];
__device__ uint2 g_W2[3072];

// ===================== helpers ==============================================
__device__ __forceinline__ float lrelu(float x) { return fmaxf(x, 0.1f * x); }

__device__ __forceinline__ uint32_t packh2(float a, float b) {
    __half2 h = __floats2half2_rn(a, b);
    return *(uint32_t*)&h;
}

// mma.sync m16n8k16 fp16 -> f32 accumulate (baseline PTX)
__device__ __forceinline__ void mmah(float c[4], const uint32_t a[4],
                                     uint32_t b0, uint32_t b1) {
    asm volatile(
        "mma.sync.aligned.m16n8k16.row.col.f32.f16.f16.f32 "
        "{%0,%1,%2,%3}, {%4,%5,%6,%7}, {%8,%9}, {%0,%1,%2,%3};"
        : "+f"(c[0]), "+f"(c[1]), "+f"(c[2]), "+f"(c[3])
        : "r"(a[0]), "r"(a[1]), "r"(a[2]), "r"(a[3]), "r"(b0), "r"(b1));
}

// ===================== prep: Wr/Wuv fp16 + pair W2 fragments ================
__global__ void prep_kernel(const float* __restrict__ cw0,
                            const float* __restrict__ cw1,
                            const float* __restrict__ cw2,
                            const float* __restrict__ cw3,
                            const float* __restrict__ mw0,
                            const float* __restrict__ mw1,
                            const float* __restrict__ mw2,
                            const float* __restrict__ mw3) {
    int idx = blockIdx.x * 256 + threadIdx.x;
    if (idx < NW) {
        int col = idx >> 9;          // n: 0..1023
        int e = idx & 511;           // k
        int p = col >> 6;
        int c = col & 63;
        const float* w; int k, t;
        if (p < 1)      { w = cw0; k = 1; t = p; }
        else if (p < 4) { w = cw1; k = 3; t = p - 1; }
        else if (p < 9) { w = cw2; k = 5; t = p - 4; }
        else            { w = cw3; k = 7; t = p - 9; }
        g_Wrh[idx] = __float2half_rn(w[(c * k + t) * EE + e]);
    } else if (idx < NW + NU) {
        int j = idx - NW;
        int n = j >> 8;              // 0..127
        int k = j & 255;
        float v;
        if (n < 64) v = mw0[n * 512 + k];
        else        v = mw0[(n - 64) * 512 + 256 + k];
        g_Wuvh[j] = __float2half_rn(v);
    } else if (idx < NW + NU + 3072) {
        int e = idx - NW - NU;
        int t4i = e & 3;
        int n = (e >> 2) & 63;
        int kc = (e >> 8) & 3;
        int l = e >> 10;
        const float* wsrc = (l == 0) ? mw1 : (l == 1) ? mw2 : mw3;
        int k0 = kc * 16 + 2 * t4i;
        float2 v01 = *(const float2*)(wsrc + n * 64 + k0);
        float2 v89 = *(const float2*)(wsrc + n * 64 + k0 + 8);
        uint2 pk;
        pk.x = packh2(v01.x, v01.y);
        pk.y = packh2(v89.x, v89.y);
        g_W2[e] = pk;
    }
}

// ===================== conv GEMM: x(f32, inline cvt) @ Wr -> G(fp16) ========
#define TSG 72            // padded k-stride in fp16 units

__global__ void __launch_bounds__(256, 1)
gemm_conv_kernel(const float* __restrict__ X,
                 const __half* __restrict__ Bg,
                 __half* __restrict__ Gh) {
    const int N = GCOLS, K = EE;
    constexpr int SA = 0;
    constexpr int SB = 128 * TSG;

    extern __shared__ __half sm[];
    int tid = threadIdx.x, w = tid >> 5, lane = tid & 31;
    int g = lane >> 2, t4 = lane & 3;
    int m0 = blockIdx.y * 128, n0 = blockIdx.x * 128;
    int mw = (w & 3) * 32;
    int nw = (w >> 2) * 64;

    float Cc[2][8][4];
#pragma unroll
    for (int mt = 0; mt < 2; mt++)
#pragma unroll
        for (int nt = 0; nt < 8; nt++)
#pragma unroll
            for (int q = 0; q < 4; q++) Cc[mt][nt][q] = 0.f;

    for (int k0 = 0; k0 < K; k0 += 64) {
        float4 af[8];
        uint4 bv[4];
#pragma unroll
        for (int it = 0; it < 8; it++) {
            int u = tid + it * 256;
            int row = u >> 4;
            int kq = (u & 15) * 4;
            af[it] = *(const float4*)(X + (m0 + row) * K + k0 + kq);
        }
#pragma unroll
        for (int it = 0; it < 4; it++) {
            int u = tid + it * 256;
            int row = u >> 3;
            int kq = (u & 7) * 8;
            bv[it] = *(const uint4*)(Bg + (n0 + row) * K + k0 + kq);
        }
        __syncthreads();
#pragma unroll
        for (int it = 0; it < 8; it++) {
            int u = tid + it * 256;
            int row = u >> 4;
            int kq = (u & 15) * 4;
            uint2 hw;
            hw.x = packh2(af[it].x, af[it].y);
            hw.y = packh2(af[it].z, af[it].w);
            *(uint2*)&sm[SA + row * TSG + kq] = hw;
        }
#pragma unroll
        for (int it = 0; it < 4; it++) {
            int u = tid + it * 256;
            int row = u >> 3;
            int kq = (u & 7) * 8;
            *(uint4*)&sm[SB + row * TSG + kq] = bv[it];
        }
        __syncthreads();

#pragma unroll
        for (int kc = 0; kc < 4; kc++) {
            int kk = kc * 16 + 2 * t4;
            uint32_t A[2][4];
#pragma unroll
            for (int mt = 0; mt < 2; mt++) {
                int r0 = mw + mt * 16 + g;
                int r1 = r0 + 8;
                A[mt][0] = *(const uint32_t*)&sm[SA + r0 * TSG + kk];
                A[mt][1] = *(const uint32_t*)&sm[SA + r1 * TSG + kk];
                A[mt][2] = *(const uint32_t*)&sm[SA + r0 * TSG + kk + 8];
                A[mt][3] = *(const uint32_t*)&sm[SA + r1 * TSG + kk + 8];
            }
#pragma unroll
            for (int nt = 0; nt < 8; nt++) {
                int nrow = nw + nt * 8 + g;
                uint32_t b0 = *(const uint32_t*)&sm[SB + nrow * TSG + kk];
                uint32_t b1 = *(const uint32_t*)&sm[SB + nrow * TSG + kk + 8];
                mmah(Cc[0][nt], A[0], b0, b1);
                mmah(Cc[1][nt], A[1], b0, b1);
            }
        }
    }

#pragma unroll
    for (int mt = 0; mt < 2; mt++) {
        int r0 = m0 + mw + mt * 16 + g;
        int r1 = r0 + 8;
#pragma unroll
        for (int nt = 0; nt < 8; nt++) {
            int col = n0 + nw + nt * 8 + 2 * t4;
            *(uint32_t*)(Gh + r0 * N + col) = packh2(Cc[mt][nt][0], Cc[mt][nt][1]);
            *(uint32_t*)(Gh + r1 * N + col) = packh2(Cc[mt][nt][2], Cc[mt][nt][3]);
        }
    }
}
#define CONV_SMEM_BYTES (2 * 128 * TSG * 2)

// ===================== fused gather + uv GEMM ===============================
// grid 64, 256 threads. Block handles 32 (l,b)-rows:
//   phase 1: gather taps from G(fp16) -> F smem [32][264] fp16
//   phase 2: stage Wuv (128x256 fp16) -> W smem [128][264]
//   phase 3: uv[32x128] = F @ Wuv^T via mma (8 warps = 2m x 4n)
#define TS2 264
#define GUV_F 0
#define GUV_W (32 * TS2)
#define GUV_SMEM_BYTES ((32 + 128) * TS2 * 2)

__global__ void __launch_bounds__(256, 1)
guv_kernel(const float* __restrict__ cb0, const float* __restrict__ cb1,
           const float* __restrict__ cb2, const float* __restrict__ cb3,
           const __half* __restrict__ Wuv, float* __restrict__ C) {
    extern __shared__ __half sm[];
    int tid = threadIdx.x, w = tid >> 5, lane = tid & 31;
    int g = lane >> 2, t4 = lane & 3;
    int row0 = blockIdx.x * 32;

    // phase 1: gather -> F (each thread: fixed channel m, 32 rows)
    {
        int m = tid;                      // first 256 elems: rows 0..? no:
        // idx = tid + it*256; row_local = idx >> 8 (0..31), m = idx & 255
        int br = (tid & 255) >> 6;
        int c = tid & 63;
        int k, base;
        const float* cb;
        if (br == 0)      { k = 1; base = 0; cb = cb0; }
        else if (br == 1) { k = 3; base = 1; cb = cb1; }
        else if (br == 2) { k = 5; base = 4; cb = cb2; }
        else              { k = 7; base = 9; cb = cb3; }
        int pad = (k - 1) >> 1;
        float bias = cb[c];
        m = tid & 255;
#pragma unroll 4
        for (int rl = 0; rl < 32; rl++) {
            int row = row0 + rl;
            int l = row >> 4, b = row & 15;
            float sum = bias;
            for (int tt = 0; tt < k; tt++) {
                int l2 = l - pad + tt;
                if ((unsigned)l2 < (unsigned)LL)
                    sum += __half2float(
                        g_Gh[(l2 * BB + b) * GCOLS + (base + tt) * 64 + c]);
            }
            sm[GUV_F + rl * TS2 + m] = __float2half_rn(lrelu(sum));
        }
    }
    // phase 2: stage Wuv [128][256] -> W smem
#pragma unroll
    for (int it = 0; it < 16; it++) {
        int u = tid + it * 256;
        int row = u >> 5;            // 0..127
        int kq = (u & 31) * 8;       // 0..248
        uint4 v = *(const uint4*)(Wuv + row * 256 + kq);
        *(uint4*)&sm[GUV_W + row * TS2 + kq] = v;
    }
    __syncthreads();

    // phase 3: GEMM 32x128x256. 8 warps: 2 along m (16 each) x 4 along n (32).
    int mw = (w & 1) * 16;
    int nw = (w >> 1) * 32;
    float Cc[4][4];
#pragma unroll
    for (int nt = 0; nt < 4; nt++)
#pragma unroll
        for (int q = 0; q < 4; q++) Cc[nt][q] = 0.f;

#pragma unroll
    for (int kc = 0; kc < 16; kc++) {
        int kk = kc * 16 + 2 * t4;
        uint32_t A[4];
        int r0 = mw + g, r1 = r0 + 8;
        A[0] = *(const uint32_t*)&sm[GUV_F + r0 * TS2 + kk];
        A[1] = *(const uint32_t*)&sm[GUV_F + r1 * TS2 + kk];
        A[2] = *(const uint32_t*)&sm[GUV_F + r0 * TS2 + kk + 8];
        A[3] = *(const uint32_t*)&sm[GUV_F + r1 * TS2 + kk + 8];
#pragma unroll
        for (int nt = 0; nt < 4; nt++) {
            int nrow = nw + nt * 8 + g;
            uint32_t b0 = *(const uint32_t*)&sm[GUV_W + nrow * TS2 + kk];
            uint32_t b1 = *(const uint32_t*)&sm[GUV_W + nrow * TS2 + kk + 8];
            mmah(Cc[nt], A, b0, b1);
        }
    }

    int r0 = row0 + mw + g, r1 = r0 + 8;
#pragma unroll
    for (int nt = 0; nt < 4; nt++) {
        int col = nw + nt * 8 + 2 * t4;
        *(float2*)(C + r0 * 128 + col) = make_float2(Cc[nt][0], Cc[nt][1]);
        *(float2*)(C + r1 * 128 + col) = make_float2(Cc[nt][2], Cc[nt][3]);
    }
}

// ===================== pair kernel (round-12 math, prepacked W2) ============
#define PV_STRIDE 132
#define P_W2   0
#define P_V    24576
#define P_U    58368
#define P_B    60416
#define P_RED  61440
#define P_SR   62464
#define P_TR   64512
#define PAIR_SMEM_BYTES 66560

__global__ void __launch_bounds__(128, 2)
pair_mma_kernel(const float* __restrict__ uv,
                const float* __restrict__ mb0, const float* __restrict__ mb1,
                const float* __restrict__ mb2, const float* __restrict__ mb3,
                const float* __restrict__ lw0, const float* __restrict__ lb0,
                const float* __restrict__ lw1, const float* __restrict__ lb1,
                float* __restrict__ out) {
    extern __shared__ char smp[];
    int tid = threadIdx.x, w = tid >> 5, lane = tid & 31;
    int g = lane >> 2, t4 = lane & 3;
    int b = blockIdx.y, j0 = blockIdx.x * 8;

    // ---- stage prepacked W2 fragments (flat copy) ----
    {
        uint2* W2s = (uint2*)(smp + P_W2);
#pragma unroll
        for (int q = 0; q < 24; q++)
            W2s[tid + 128 * q] = g_W2[tid + 128 * q];
    }
    // ---- stage V[k][i] (f32, stride 132) ----
    {
        float* V = (float*)(smp + P_V);
        const float* vp = uv + (tid * BB + b) * 128 + 64;
#pragma unroll
        for (int q = 0; q < 16; q++) {
            float4 v4 = *(const float4*)(vp + q * 4);
            V[(q * 4 + 0) * PV_STRIDE + tid] = v4.x;
            V[(q * 4 + 1) * PV_STRIDE + tid] = v4.y;
            V[(q * 4 + 2) * PV_STRIDE + tid] = v4.z;
            V[(q * 4 + 3) * PV_STRIDE + tid] = v4.w;
        }
    }
    if (tid < 64) {
        float* U = (float*)(smp + P_U);
#pragma unroll
        for (int jt = 0; jt < 8; jt++)
            U[jt * 64 + tid] = uv[((j0 + jt) * BB + b) * 128 + tid];
        float* Bs = (float*)(smp + P_B);
        Bs[tid] = mb0[tid];
        Bs[64 + tid] = mb1[tid];
        Bs[128 + tid] = mb2[tid];
        Bs[192 + tid] = mb3[tid];
    }
    __syncthreads();

    const float* V = (const float*)(smp + P_V);
    const float* U = (const float*)(smp + P_U);
    const float* BIAS = (const float*)(smp + P_B);
    const uint2* W2 = (const uint2*)(smp + P_W2);
    float* RED = (float*)(smp + P_RED);
    float* SR = (float*)(smp + P_SR);

    for (int jt = 0; jt < 8; jt++) {
        uint32_t A[2][4][4];

        // ---- layer-1 A fragments: x = lrelu(u + v + b0), single fp16 ----
#pragma unroll
        for (int mt = 0; mt < 2; mt++) {
            int r0 = w * 32 + mt * 16 + g;
            int r1 = r0 + 8;
#pragma unroll
            for (int kc = 0; kc < 4; kc++) {
                int k0 = kc * 16 + 2 * t4;
                float ub0 = U[jt * 64 + k0]     + BIAS[k0];
                float ub1 = U[jt * 64 + k0 + 1] + BIAS[k0 + 1];
                float ub8 = U[jt * 64 + k0 + 8] + BIAS[k0 + 8];
                float ub9 = U[jt * 64 + k0 + 9] + BIAS[k0 + 9];
                float x00 = lrelu(ub0 + V[k0 * PV_STRIDE + r0]);
                float x01 = lrelu(ub1 + V[(k0 + 1) * PV_STRIDE + r0]);
                float x10 = lrelu(ub0 + V[k0 * PV_STRIDE + r1]);
                float x11 = lrelu(ub1 + V[(k0 + 1) * PV_STRIDE + r1]);
                float x08 = lrelu(ub8 + V[(k0 + 8) * PV_STRIDE + r0]);
                float x09 = lrelu(ub9 + V[(k0 + 9) * PV_STRIDE + r0]);
                float x18 = lrelu(ub8 + V[(k0 + 8) * PV_STRIDE + r1]);
                float x19 = lrelu(ub9 + V[(k0 + 9) * PV_STRIDE + r1]);
                A[mt][kc][0] = packh2(x00, x01);
                A[mt][kc][1] = packh2(x10, x11);
                A[mt][kc][2] = packh2(x08, x09);
                A[mt][kc][3] = packh2(x18, x19);
            }
        }

        // ---- 3 chained MMA layers (single-term: A*W) ----
        float Cc[2][8][4];
#pragma unroll
        for (int l = 0; l < 3; l++) {
#pragma unroll
            for (int mt = 0; mt < 2; mt++)
#pragma unroll
                for (int nt = 0; nt < 8; nt++)
#pragma unroll
                    for (int q = 0; q < 4; q++) Cc[mt][nt][q] = 0.f;

#pragma unroll
            for (int kc = 0; kc < 4; kc++) {
#pragma unroll
                for (int nt = 0; nt < 8; nt++) {
                    uint2 wq = W2[((l * 4 + kc) * 64 + nt * 8 + g) * 4 + t4];
                    mmah(Cc[0][nt], A[0][kc], wq.x, wq.y);
                    mmah(Cc[1][nt], A[1][kc], wq.x, wq.y);
                }
            }

            if (l < 2) {
                const float* bl = BIAS + 64 * (l + 1);
#pragma unroll
                for (int nt = 0; nt < 8; nt++) {
                    int col = nt * 8 + 2 * t4;
                    float bx = bl[col], by = bl[col + 1];
                    int kc2 = nt >> 1, ri = (nt & 1) * 2;
#pragma unroll
                    for (int mt = 0; mt < 2; mt++) {
                        float h0 = lrelu(Cc[mt][nt][0] + bx);
                        float h1 = lrelu(Cc[mt][nt][1] + by);
                        float h2 = lrelu(Cc[mt][nt][2] + bx);
                        float h3 = lrelu(Cc[mt][nt][3] + by);
                        A[mt][kc2][ri]     = packh2(h0, h1);
                        A[mt][kc2][ri + 1] = packh2(h2, h3);
                    }
                }
            }
        }

        // ---- final: bias + lrelu, reduce over i ----
        {
            const float* bl = BIAS + 192;
#pragma unroll
            for (int nt = 0; nt < 8; nt++) {
                int col = nt * 8 + 2 * t4;
                float bx = bl[col], by = bl[col + 1];
                float s0 = lrelu(Cc[0][nt][0] + bx) + lrelu(Cc[0][nt][2] + bx) +
                           lrelu(Cc[1][nt][0] + bx) + lrelu(Cc[1][nt][2] + bx);
                float s1 = lrelu(Cc[0][nt][1] + by) + lrelu(Cc[0][nt][3] + by) +
                           lrelu(Cc[1][nt][1] + by) + lrelu(Cc[1][nt][3] + by);
                s0 += __shfl_xor_sync(0xffffffffu, s0, 4);
                s0 += __shfl_xor_sync(0xffffffffu, s0, 8);
                s0 += __shfl_xor_sync(0xffffffffu, s0, 16);
                s1 += __shfl_xor_sync(0xffffffffu, s1, 4);
                s1 += __shfl_xor_sync(0xffffffffu, s1, 8);
                s1 += __shfl_xor_sync(0xffffffffu, s1, 16);
                if (lane < 4) {
                    RED[w * 64 + col] = s0;
                    RED[w * 64 + col + 1] = s1;
                }
            }
        }
        __syncthreads();
        if (tid < 64) {
            float s = RED[tid] + RED[64 + tid] + RED[128 + tid] + RED[192 + tid];
            SR[jt * 64 + tid] = s;
        }
        __syncthreads();
    }

    // ---- fused head: t = lrelu(s@lw0.T+lb0); out = lrelu(t@lw1.T+lb1) ----
    float* TR = (float*)(smp + P_TR);
#pragma unroll
    for (int q = 0; q < 4; q++) {
        int idx = tid + 128 * q;
        int jt = idx >> 6, o = idx & 63;
        const float* wr = lw0 + o * 64;
        float acc = lb0[o];
#pragma unroll
        for (int c = 0; c < 64; c += 4) {
            float4 w4 = *(const float4*)(wr + c);
            acc += SR[jt * 64 + c] * w4.x + SR[jt * 64 + c + 1] * w4.y +
                   SR[jt * 64 + c + 2] * w4.z + SR[jt * 64 + c + 3] * w4.w;
        }
        TR[idx] = lrelu(acc);
    }
    __syncthreads();
#pragma unroll
    for (int q = 0; q < 16; q++) {
        int idx = tid + 128 * q;
        int jt = idx >> 8, o = idx & 255;
        const float* wr = lw1 + o * 64;
        float acc = lb1[o];
#pragma unroll
        for (int c = 0; c < 64; c += 4) {
            float4 w4 = *(const float4*)(wr + c);
            acc += TR[jt * 64 + c] * w4.x + TR[jt * 64 + c + 1] * w4.y +
                   TR[jt * 64 + c + 2] * w4.z + TR[jt * 64 + c + 3] * w4.w;
        }
        out[((j0 + jt) * BB + b) * 256 + o] = lrelu(acc);
    }
}

// ===================== host launch ==========================================
extern "C" void kernel_launch(void* const* d_in, const int* in_sizes, int n_in,
                              void* d_out, int out_size) {
    const float* x   = (const float*)d_in[0];
    const float* cw0 = (const float*)d_in[1];
    const float* cb0 = (const float*)d_in[2];
    const float* cw1 = (const float*)d_in[3];
    const float* cb1 = (const float*)d_in[4];
    const float* cw2 = (const float*)d_in[5];
    const float* cb2 = (const float*)d_in[6];
    const float* cw3 = (const float*)d_in[7];
    const float* cb3 = (const float*)d_in[8];
    const float* mw0 = (const float*)d_in[9];
    const float* mb0 = (const float*)d_in[10];
    const float* mw1 = (const float*)d_in[11];
    const float* mb1 = (const float*)d_in[12];
    const float* mw2 = (const float*)d_in[13];
    const float* mb2 = (const float*)d_in[14];
    const float* mw3 = (const float*)d_in[15];
    const float* mb3 = (const float*)d_in[16];
    const float* lw0 = (const float*)d_in[17];
    const float* lb0 = (const float*)d_in[18];
    const float* lw1 = (const float*)d_in[19];
    const float* lb1 = (const float*)d_in[20];
    float* out = (float*)d_out;

    float* uvb;
    __half *Gh, *Wrh, *Wuvh;
    cudaGetSymbolAddress((void**)&Gh, g_Gh);
    cudaGetSymbolAddress((void**)&uvb, g_uv);
    cudaGetSymbolAddress((void**)&Wrh, g_Wrh);
    cudaGetSymbolAddress((void**)&Wuvh, g_Wuvh);

    // 1) prep (weights + pair W2 fragments)
    prep_kernel<<<(NW + NU + 3072 + 255) / 256, 256>>>(
        cw0, cw1, cw2, cw3, mw0, mw1, mw2, mw3);

    // 2) conv as GEMM: G = x @ Wr (x cvt inline, G fp16)
    cudaFuncSetAttribute(gemm_conv_kernel,
                         cudaFuncAttributeMaxDynamicSharedMemorySize,
                         CONV_SMEM_BYTES);
    gemm_conv_kernel<<<dim3(GCOLS / 128, ROWS / 128), 256, CONV_SMEM_BYTES>>>(
        x, Wrh, Gh);

    // 3) fused gather + uv GEMM
    cudaFuncSetAttribute(guv_kernel,
                         cudaFuncAttributeMaxDynamicSharedMemorySize,
                         GUV_SMEM_BYTES);
    guv_kernel<<<64, 256, GUV_SMEM_BYTES>>>(cb0, cb1, cb2, cb3, Wuvh, uvb);

    // 4) pair stage + fused head
    cudaFuncSetAttribute(pair_mma_kernel,
                         cudaFuncAttributeMaxDynamicSharedMemorySize,
                         PAIR_SMEM_BYTES);
    pair_mma_kernel<<<dim3(16, 16), 128, PAIR_SMEM_BYTES>>>(
        uvb, mb0, mb1, mb2, mb3, lw0, lb0, lw1, lb1, out);
}

// round 15
// speedup vs baseline: 1.3516x; 1.3516x over previous
#include <cuda_runtime.h>
#include <cuda_bf16.h>
#include <cuda_fp16.h>
#include <cstdint>

// ---------------------------------------------------------------------------
// RelationLayer: L=128, B=16, E=512, C=64, KERNELS={1,3,5,7}, M=256, OUT=256
//  1) prep: conv weights -> fp16, Wuv -> fp16, pair W2 fragments packed
//  2) G = x(2048x512) @ Wr    (fp16 GEMM, x converted inline, G stored fp16)
//  3) f = lrelu(gather taps + bias) -> fp16           (round-13 kernel)
//  4) uv = f(2048x256) @ Wuv  (full-K single-phase)   (round-13 kernel)
//  5) pair kernel: pure fp16 MMA, prepacked W2, V staged fp16 row-major.
// ---------------------------------------------------------------------------

#define LL 128
#define BB 16
#define EE 512
#define MM 256
#define ROWS 2048
#define GCOLS 1024

#define NW (EE * GCOLS)
#define NU (128 * MM)
#define NF (ROWS * MM)

__device__ __half g_Gh[ROWS * GCOLS];
__device__ float g_uv[ROWS * 128];
__device__ __half g_ff[NF];
__device__ __half g_Wrh[NW];
__device__ __half g_Wuvh[NU];
__device__ uint2 g_W2[3072];

// ===================== helpers ==============================================
__device__ __forceinline__ float lrelu(float x) { return fmaxf(x, 0.1f * x); }

__device__ __forceinline__ uint32_t packh2(float a, float b) {
    __half2 h = __floats2half2_rn(a, b);
    return *(uint32_t*)&h;
}

// mma.sync m16n8k16 fp16 -> f32 accumulate (baseline PTX)
__device__ __forceinline__ void mmah(float c[4], const uint32_t a[4],
                                     uint32_t b0, uint32_t b1) {
    asm volatile(
        "mma.sync.aligned.m16n8k16.row.col.f32.f16.f16.f32 "
        "{%0,%1,%2,%3}, {%4,%5,%6,%7}, {%8,%9}, {%0,%1,%2,%3};"
        : "+f"(c[0]), "+f"(c[1]), "+f"(c[2]), "+f"(c[3])
        : "r"(a[0]), "r"(a[1]), "r"(a[2]), "r"(a[3]), "r"(b0), "r"(b1));
}

// ===================== prep: Wr/Wuv fp16 + pair W2 fragments ================
__global__ void prep_kernel(const float* __restrict__ cw0,
                            const float* __restrict__ cw1,
                            const float* __restrict__ cw2,
                            const float* __restrict__ cw3,
                            const float* __restrict__ mw0,
                            const float* __restrict__ mw1,
                            const float* __restrict__ mw2,
                            const float* __restrict__ mw3) {
    int idx = blockIdx.x * 256 + threadIdx.x;
    if (idx < NW) {
        int col = idx >> 9;          // n: 0..1023
        int e = idx & 511;           // k
        int p = col >> 6;
        int c = col & 63;
        const float* w; int k, t;
        if (p < 1)      { w = cw0; k = 1; t = p; }
        else if (p < 4) { w = cw1; k = 3; t = p - 1; }
        else if (p < 9) { w = cw2; k = 5; t = p - 4; }
        else            { w = cw3; k = 7; t = p - 9; }
        g_Wrh[idx] = __float2half_rn(w[(c * k + t) * EE + e]);
    } else if (idx < NW + NU) {
        int j = idx - NW;
        int n = j >> 8;              // 0..127
        int k = j & 255;
        float v;
        if (n < 64) v = mw0[n * 512 + k];
        else        v = mw0[(n - 64) * 512 + 256 + k];
        g_Wuvh[j] = __float2half_rn(v);
    } else if (idx < NW + NU + 3072) {
        int e = idx - NW - NU;
        int t4i = e & 3;
        int n = (e >> 2) & 63;
        int kc = (e >> 8) & 3;
        int l = e >> 10;
        const float* wsrc = (l == 0) ? mw1 : (l == 1) ? mw2 : mw3;
        int k0 = kc * 16 + 2 * t4i;
        float2 v01 = *(const float2*)(wsrc + n * 64 + k0);
        float2 v89 = *(const float2*)(wsrc + n * 64 + k0 + 8);
        uint2 pk;
        pk.x = packh2(v01.x, v01.y);
        pk.y = packh2(v89.x, v89.y);
        g_W2[e] = pk;
    }
}

// ===================== conv GEMM: x(f32, inline cvt) @ Wr -> G(fp16) ========
#define TSG 72            // padded k-stride in fp16 units

__global__ void __launch_bounds__(256, 1)
gemm_conv_kernel(const float* __restrict__ X,
                 const __half* __restrict__ Bg,
                 __half* __restrict__ Gh) {
    const int N = GCOLS, K = EE;
    constexpr int SA = 0;
    constexpr int SB = 128 * TSG;

    extern __shared__ __half sm[];
    int tid = threadIdx.x, w = tid >> 5, lane = tid & 31;
    int g = lane >> 2, t4 = lane & 3;
    int m0 = blockIdx.y * 128, n0 = blockIdx.x * 128;
    int mw = (w & 3) * 32;
    int nw = (w >> 2) * 64;

    float Cc[2][8][4];
#pragma unroll
    for (int mt = 0; mt < 2; mt++)
#pragma unroll
        for (int nt = 0; nt < 8; nt++)
#pragma unroll
            for (int q = 0; q < 4; q++) Cc[mt][nt][q] = 0.f;

    for (int k0 = 0; k0 < K; k0 += 64) {
        float4 af[8];
        uint4 bv[4];
#pragma unroll
        for (int it = 0; it < 8; it++) {
            int u = tid + it * 256;
            int row = u >> 4;
            int kq = (u & 15) * 4;
            af[it] = *(const float4*)(X + (m0 + row) * K + k0 + kq);
        }
#pragma unroll
        for (int it = 0; it < 4; it++) {
            int u = tid + it * 256;
            int row = u >> 3;
            int kq = (u & 7) * 8;
            bv[it] = *(const uint4*)(Bg + (n0 + row) * K + k0 + kq);
        }
        __syncthreads();
#pragma unroll
        for (int it = 0; it < 8; it++) {
            int u = tid + it * 256;
            int row = u >> 4;
            int kq = (u & 15) * 4;
            uint2 hw;
            hw.x = packh2(af[it].x, af[it].y);
            hw.y = packh2(af[it].z, af[it].w);
            *(uint2*)&sm[SA + row * TSG + kq] = hw;
        }
#pragma unroll
        for (int it = 0; it < 4; it++) {
            int u = tid + it * 256;
            int row = u >> 3;
            int kq = (u & 7) * 8;
            *(uint4*)&sm[SB + row * TSG + kq] = bv[it];
        }
        __syncthreads();

#pragma unroll
        for (int kc = 0; kc < 4; kc++) {
            int kk = kc * 16 + 2 * t4;
            uint32_t A[2][4];
#pragma unroll
            for (int mt = 0; mt < 2; mt++) {
                int r0 = mw + mt * 16 + g;
                int r1 = r0 + 8;
                A[mt][0] = *(const uint32_t*)&sm[SA + r0 * TSG + kk];
                A[mt][1] = *(const uint32_t*)&sm[SA + r1 * TSG + kk];
                A[mt][2] = *(const uint32_t*)&sm[SA + r0 * TSG + kk + 8];
                A[mt][3] = *(const uint32_t*)&sm[SA + r1 * TSG + kk + 8];
            }
#pragma unroll
            for (int nt = 0; nt < 8; nt++) {
                int nrow = nw + nt * 8 + g;
                uint32_t b0 = *(const uint32_t*)&sm[SB + nrow * TSG + kk];
                uint32_t b1 = *(const uint32_t*)&sm[SB + nrow * TSG + kk + 8];
                mmah(Cc[0][nt], A[0], b0, b1);
                mmah(Cc[1][nt], A[1], b0, b1);
            }
        }
    }

#pragma unroll
    for (int mt = 0; mt < 2; mt++) {
        int r0 = m0 + mw + mt * 16 + g;
        int r1 = r0 + 8;
#pragma unroll
        for (int nt = 0; nt < 8; nt++) {
            int col = n0 + nw + nt * 8 + 2 * t4;
            *(uint32_t*)(Gh + r0 * N + col) = packh2(Cc[mt][nt][0], Cc[mt][nt][1]);
            *(uint32_t*)(Gh + r1 * N + col) = packh2(Cc[mt][nt][2], Cc[mt][nt][3]);
        }
    }
}
#define CONV_SMEM_BYTES (2 * 128 * TSG * 2)

// ===================== gather taps -> f (fp16 in/out, ILP 8) ================
__global__ void gather_f_kernel(const float* __restrict__ cb0,
                                const float* __restrict__ cb1,
                                const float* __restrict__ cb2,
                                const float* __restrict__ cb3) {
    int t0 = blockIdx.x * 256 + threadIdx.x;   // 0..65535
#pragma unroll
    for (int q = 0; q < 8; q++) {
        int idx = t0 + q * 65536;
        int row = idx >> 8;        // (l,b): 0..2047
        int m = idx & 255;
        int l = row >> 4, b = row & 15;
        int br = m >> 6, c = m & 63;
        int k, pad, base;
        const float* cb;
        if (br == 0)      { k = 1; base = 0; cb = cb0; }
        else if (br == 1) { k = 3; base = 1; cb = cb1; }
        else if (br == 2) { k = 5; base = 4; cb = cb2; }
        else              { k = 7; base = 9; cb = cb3; }
        pad = (k - 1) >> 1;
        float sum = cb[c];
        for (int tt = 0; tt < k; tt++) {
            int l2 = l - pad + tt;
            if ((unsigned)l2 < (unsigned)LL)
                sum += __half2float(g_Gh[(l2 * BB + b) * GCOLS + (base + tt) * 64 + c]);
        }
        g_ff[idx] = __float2half_rn(lrelu(sum));
    }
}

// ===================== uv GEMM: full-K single-phase fp16 ====================
#define TS2 264           // padded k-stride for K=256

__global__ void __launch_bounds__(256, 1)
gemm_uv_kernel(const __half* __restrict__ Ag,
               const __half* __restrict__ Bg,
               float* __restrict__ C) {
    const int N = 128, K = 256;
    constexpr int SA = 0;
    constexpr int SB = 64 * TS2;

    extern __shared__ __half sm[];
    int tid = threadIdx.x, w = tid >> 5, lane = tid & 31;
    int g = lane >> 2, t4 = lane & 3;
    int m0 = blockIdx.y * 64, n0 = blockIdx.x * 64;
    int mw = (w & 3) * 16;
    int nw = (w >> 2) * 32;

    uint4 av[8], bv[8];
#pragma unroll
    for (int it = 0; it < 8; it++) {
        int u = tid + it * 256;
        int row = u >> 5;
        int kq = (u & 31) * 8;
        av[it] = *(const uint4*)(Ag + (m0 + row) * K + kq);
        bv[it] = *(const uint4*)(Bg + (n0 + row) * K + kq);
    }
#pragma unroll
    for (int it = 0; it < 8; it++) {
        int u = tid + it * 256;
        int row = u >> 5;
        int kq = (u & 31) * 8;
        *(uint4*)&sm[SA + row * TS2 + kq] = av[it];
        *(uint4*)&sm[SB + row * TS2 + kq] = bv[it];
    }
    __syncthreads();

    float Cc[4][4];
#pragma unroll
    for (int nt = 0; nt < 4; nt++)
#pragma unroll
        for (int q = 0; q < 4; q++) Cc[nt][q] = 0.f;

#pragma unroll
    for (int kc = 0; kc < 16; kc++) {
        int kk = kc * 16 + 2 * t4;
        uint32_t A[4];
        int r0 = mw + g, r1 = r0 + 8;
        A[0] = *(const uint32_t*)&sm[SA + r0 * TS2 + kk];
        A[1] = *(const uint32_t*)&sm[SA + r1 * TS2 + kk];
        A[2] = *(const uint32_t*)&sm[SA + r0 * TS2 + kk + 8];
        A[3] = *(const uint32_t*)&sm[SA + r1 * TS2 + kk + 8];
#pragma unroll
        for (int nt = 0; nt < 4; nt++) {
            int nrow = nw + nt * 8 + g;
            uint32_t b0 = *(const uint32_t*)&sm[SB + nrow * TS2 + kk];
            uint32_t b1 = *(const uint32_t*)&sm[SB + nrow * TS2 + kk + 8];
            mmah(Cc[nt], A, b0, b1);
        }
    }

    int r0 = m0 + mw + g, r1 = r0 + 8;
#pragma unroll
    for (int nt = 0; nt < 4; nt++) {
        int col = n0 + nw + nt * 8 + 2 * t4;
        *(float2*)(C + r0 * N + col) = make_float2(Cc[nt][0], Cc[nt][1]);
        *(float2*)(C + r1 * N + col) = make_float2(Cc[nt][2], Cc[nt][3]);
    }
}
#define UV_SMEM_BYTES (2 * 64 * TS2 * 2)

// ===================== pair kernel (V fp16 row-major, prepacked W2) =========
// grid (16,16), 128 threads. V stored as fp16 [i][72] (GEMM A-fragment layout).
#define PVH 72
#define P_W2   0
#define P_V    24576
#define P_U    43008
#define P_B    45056
#define P_RED  46080
#define P_SR   47104
#define P_TR   49152
#define PAIR_SMEM_BYTES 51200

__global__ void __launch_bounds__(128, 2)
pair_mma_kernel(const float* __restrict__ uv,
                const float* __restrict__ mb0, const float* __restrict__ mb1,
                const float* __restrict__ mb2, const float* __restrict__ mb3,
                const float* __restrict__ lw0, const float* __restrict__ lb0,
                const float* __restrict__ lw1, const float* __restrict__ lb1,
                float* __restrict__ out) {
    extern __shared__ char smp[];
    int tid = threadIdx.x, w = tid >> 5, lane = tid & 31;
    int g = lane >> 2, t4 = lane & 3;
    int b = blockIdx.y, j0 = blockIdx.x * 8;

    // ---- stage prepacked W2 fragments (flat copy) ----
    {
        uint2* W2s = (uint2*)(smp + P_W2);
#pragma unroll
        for (int q = 0; q < 24; q++)
            W2s[tid + 128 * q] = g_W2[tid + 128 * q];
    }
    // ---- stage V as fp16 [i][PVH]: thread = row i ----
    {
        __half* Vh = (__half*)(smp + P_V);
        const float* vp = uv + (tid * BB + b) * 128 + 64;
#pragma unroll
        for (int q = 0; q < 16; q++) {
            float4 v4 = *(const float4*)(vp + q * 4);
            uint2 hw;
            hw.x = packh2(v4.x, v4.y);
            hw.y = packh2(v4.z, v4.w);
            *(uint2*)&Vh[tid * PVH + q * 4] = hw;
        }
    }
    if (tid < 64) {
        float* U = (float*)(smp + P_U);
#pragma unroll
        for (int jt = 0; jt < 8; jt++)
            U[jt * 64 + tid] = uv[((j0 + jt) * BB + b) * 128 + tid];
        float* Bs = (float*)(smp + P_B);
        Bs[tid] = mb0[tid];
        Bs[64 + tid] = mb1[tid];
        Bs[128 + tid] = mb2[tid];
        Bs[192 + tid] = mb3[tid];
    }
    __syncthreads();

    const __half* Vh = (const __half*)(smp + P_V);
    const float* U = (const float*)(smp + P_U);
    const float* BIAS = (const float*)(smp + P_B);
    const uint2* W2 = (const uint2*)(smp + P_W2);
    float* RED = (float*)(smp + P_RED);
    float* SR = (float*)(smp + P_SR);

    for (int jt = 0; jt < 8; jt++) {
        uint32_t A[2][4][4];

        // ---- layer-1 A fragments: x = lrelu(u + v + b0), V loads A-style ----
#pragma unroll
        for (int mt = 0; mt < 2; mt++) {
            int r0 = w * 32 + mt * 16 + g;
            int r1 = r0 + 8;
#pragma unroll
            for (int kc = 0; kc < 4; kc++) {
                int k0 = kc * 16 + 2 * t4;
                float ub0 = U[jt * 64 + k0]     + BIAS[k0];
                float ub1 = U[jt * 64 + k0 + 1] + BIAS[k0 + 1];
                float ub8 = U[jt * 64 + k0 + 8] + BIAS[k0 + 8];
                float ub9 = U[jt * 64 + k0 + 9] + BIAS[k0 + 9];
                __half2 va0 = *(const __half2*)&Vh[r0 * PVH + k0];
                __half2 va8 = *(const __half2*)&Vh[r0 * PVH + k0 + 8];
                __half2 vb0 = *(const __half2*)&Vh[r1 * PVH + k0];
                __half2 vb8 = *(const __half2*)&Vh[r1 * PVH + k0 + 8];
                float2 fa0 = __half22float2(va0);
                float2 fa8 = __half22float2(va8);
                float2 fb0 = __half22float2(vb0);
                float2 fb8 = __half22float2(vb8);
                float x00 = lrelu(ub0 + fa0.x);
                float x01 = lrelu(ub1 + fa0.y);
                float x10 = lrelu(ub0 + fb0.x);
                float x11 = lrelu(ub1 + fb0.y);
                float x08 = lrelu(ub8 + fa8.x);
                float x09 = lrelu(ub9 + fa8.y);
                float x18 = lrelu(ub8 + fb8.x);
                float x19 = lrelu(ub9 + fb8.y);
                A[mt][kc][0] = packh2(x00, x01);
                A[mt][kc][1] = packh2(x10, x11);
                A[mt][kc][2] = packh2(x08, x09);
                A[mt][kc][3] = packh2(x18, x19);
            }
        }

        // ---- 3 chained MMA layers (single-term: A*W) ----
        float Cc[2][8][4];
#pragma unroll
        for (int l = 0; l < 3; l++) {
#pragma unroll
            for (int mt = 0; mt < 2; mt++)
#pragma unroll
                for (int nt = 0; nt < 8; nt++)
#pragma unroll
                    for (int q = 0; q < 4; q++) Cc[mt][nt][q] = 0.f;

#pragma unroll
            for (int kc = 0; kc < 4; kc++) {
#pragma unroll
                for (int nt = 0; nt < 8; nt++) {
                    uint2 wq = W2[((l * 4 + kc) * 64 + nt * 8 + g) * 4 + t4];
                    mmah(Cc[0][nt], A[0][kc], wq.x, wq.y);
                    mmah(Cc[1][nt], A[1][kc], wq.x, wq.y);
                }
            }

            if (l < 2) {
                const float* bl = BIAS + 64 * (l + 1);
#pragma unroll
                for (int nt = 0; nt < 8; nt++) {
                    int col = nt * 8 + 2 * t4;
                    float bx = bl[col], by = bl[col + 1];
                    int kc2 = nt >> 1, ri = (nt & 1) * 2;
#pragma unroll
                    for (int mt = 0; mt < 2; mt++) {
                        float h0 = lrelu(Cc[mt][nt][0] + bx);
                        float h1 = lrelu(Cc[mt][nt][1] + by);
                        float h2 = lrelu(Cc[mt][nt][2] + bx);
                        float h3 = lrelu(Cc[mt][nt][3] + by);
                        A[mt][kc2][ri]     = packh2(h0, h1);
                        A[mt][kc2][ri + 1] = packh2(h2, h3);
                    }
                }
            }
        }

        // ---- final: bias + lrelu, reduce over i ----
        {
            const float* bl = BIAS + 192;
#pragma unroll
            for (int nt = 0; nt < 8; nt++) {
                int col = nt * 8 + 2 * t4;
                float bx = bl[col], by = bl[col + 1];
                float s0 = lrelu(Cc[0][nt][0] + bx) + lrelu(Cc[0][nt][2] + bx) +
                           lrelu(Cc[1][nt][0] + bx) + lrelu(Cc[1][nt][2] + bx);
                float s1 = lrelu(Cc[0][nt][1] + by) + lrelu(Cc[0][nt][3] + by) +
                           lrelu(Cc[1][nt][1] + by) + lrelu(Cc[1][nt][3] + by);
                s0 += __shfl_xor_sync(0xffffffffu, s0, 4);
                s0 += __shfl_xor_sync(0xffffffffu, s0, 8);
                s0 += __shfl_xor_sync(0xffffffffu, s0, 16);
                s1 += __shfl_xor_sync(0xffffffffu, s1, 4);
                s1 += __shfl_xor_sync(0xffffffffu, s1, 8);
                s1 += __shfl_xor_sync(0xffffffffu, s1, 16);
                if (lane < 4) {
                    RED[w * 64 + col] = s0;
                    RED[w * 64 + col + 1] = s1;
                }
            }
        }
        __syncthreads();
        if (tid < 64) {
            float s = RED[tid] + RED[64 + tid] + RED[128 + tid] + RED[192 + tid];
            SR[jt * 64 + tid] = s;
        }
        __syncthreads();
    }

    // ---- fused head: t = lrelu(s@lw0.T+lb0); out = lrelu(t@lw1.T+lb1) ----
    float* TR = (float*)(smp + P_TR);
#pragma unroll
    for (int q = 0; q < 4; q++) {
        int idx = tid + 128 * q;
        int jt = idx >> 6, o = idx & 63;
        const float* wr = lw0 + o * 64;
        float acc = lb0[o];
#pragma unroll
        for (int c = 0; c < 64; c += 4) {
            float4 w4 = *(const float4*)(wr + c);
            acc += SR[jt * 64 + c] * w4.x + SR[jt * 64 + c + 1] * w4.y +
                   SR[jt * 64 + c + 2] * w4.z + SR[jt * 64 + c + 3] * w4.w;
        }
        TR[idx] = lrelu(acc);
    }
    __syncthreads();
#pragma unroll
    for (int q = 0; q < 16; q++) {
        int idx = tid + 128 * q;
        int jt = idx >> 8, o = idx & 255;
        const float* wr = lw1 + o * 64;
        float acc = lb1[o];
#pragma unroll
        for (int c = 0; c < 64; c += 4) {
            float4 w4 = *(const float4*)(wr + c);
            acc += TR[jt * 64 + c] * w4.x + TR[jt * 64 + c + 1] * w4.y +
                   TR[jt * 64 + c + 2] * w4.z + TR[jt * 64 + c + 3] * w4.w;
        }
        out[((j0 + jt) * BB + b) * 256 + o] = lrelu(acc);
    }
}

// ===================== host launch ==========================================
extern "C" void kernel_launch(void* const* d_in, const int* in_sizes, int n_in,
                              void* d_out, int out_size) {
    const float* x   = (const float*)d_in[0];
    const float* cw0 = (const float*)d_in[1];
    const float* cb0 = (const float*)d_in[2];
    const float* cw1 = (const float*)d_in[3];
    const float* cb1 = (const float*)d_in[4];
    const float* cw2 = (const float*)d_in[5];
    const float* cb2 = (const float*)d_in[6];
    const float* cw3 = (const float*)d_in[7];
    const float* cb3 = (const float*)d_in[8];
    const float* mw0 = (const float*)d_in[9];
    const float* mb0 = (const float*)d_in[10];
    const float* mw1 = (const float*)d_in[11];
    const float* mb1 = (const float*)d_in[12];
    const float* mw2 = (const float*)d_in[13];
    const float* mb2 = (const float*)d_in[14];
    const float* mw3 = (const float*)d_in[15];
    const float* mb3 = (const float*)d_in[16];
    const float* lw0 = (const float*)d_in[17];
    const float* lb0 = (const float*)d_in[18];
    const float* lw1 = (const float*)d_in[19];
    const float* lb1 = (const float*)d_in[20];
    float* out = (float*)d_out;

    float* uvb;
    __half *Gh, *ff, *Wrh, *Wuvh;
    cudaGetSymbolAddress((void**)&Gh, g_Gh);
    cudaGetSymbolAddress((void**)&uvb, g_uv);
    cudaGetSymbolAddress((void**)&ff, g_ff);
    cudaGetSymbolAddress((void**)&Wrh, g_Wrh);
    cudaGetSymbolAddress((void**)&Wuvh, g_Wuvh);

    // 1) prep (weights + pair W2 fragments)
    prep_kernel<<<(NW + NU + 3072 + 255) / 256, 256>>>(
        cw0, cw1, cw2, cw3, mw0, mw1, mw2, mw3);

    // 2) conv as GEMM: G = x @ Wr (x cvt inline, G fp16)
    cudaFuncSetAttribute(gemm_conv_kernel,
                         cudaFuncAttributeMaxDynamicSharedMemorySize,
                         CONV_SMEM_BYTES);
    gemm_conv_kernel<<<dim3(GCOLS / 128, ROWS / 128), 256, CONV_SMEM_BYTES>>>(
        x, Wrh, Gh);

    // 3) gather taps -> f (fp16)
    gather_f_kernel<<<256, 256>>>(cb0, cb1, cb2, cb3);

    // 4) uv = f @ Wuv (full-K single-phase, 64x64 tiles)
    cudaFuncSetAttribute(gemm_uv_kernel,
                         cudaFuncAttributeMaxDynamicSharedMemorySize,
                         UV_SMEM_BYTES);
    gemm_uv_kernel<<<dim3(2, ROWS / 64), 256, UV_SMEM_BYTES>>>(
        ff, Wuvh, uvb);

    // 5) pair stage + fused head
    cudaFuncSetAttribute(pair_mma_kernel,
                         cudaFuncAttributeMaxDynamicSharedMemorySize,
                         PAIR_SMEM_BYTES);
    pair_mma_kernel<<<dim3(16, 16), 128, PAIR_SMEM_BYTES>>>(
        uvb, mb0, mb1, mb2, mb3, lw0, lb0, lw1, lb1, out);
}

// round 16
// speedup vs baseline: 1.3559x; 1.0032x over previous
#include <cuda_runtime.h>
#include <cuda_bf16.h>
#include <cuda_fp16.h>
#include <cstdint>

// ---------------------------------------------------------------------------
// RelationLayer: L=128, B=16, E=512, C=64, KERNELS={1,3,5,7}, M=256, OUT=256
//  1) prep: conv weights -> fp16, Wuv -> fp16, pair W4 fragments (80B stride)
//  2) G = x(2048x512) @ Wr    (fp16 GEMM, x converted inline, G stored fp16)
//  3) f = lrelu(gather taps + bias) -> fp16
//  4) uv = f(2048x256) @ Wuv  (full-K single-phase)
//  5) pair kernel: pure fp16 MMA, LDS.128 weight fragments, V fp16 row-major.
// ---------------------------------------------------------------------------

#define LL 128
#define BB 16
#define EE 512
#define MM 256
#define ROWS 2048
#define GCOLS 1024

#define NW (EE * GCOLS)
#define NU (128 * MM)
#define NF (ROWS * MM)

__device__ __half g_Gh[ROWS * GCOLS];
__device__ float g_uv[ROWS * 128];
__device__ __half g_ff[NF];
__device__ __half g_Wrh[NW];
__device__ __half g_Wuvh[NU];
__device__ uint2 g_W4[3840];          // 384 entries x 80B (64B data + 16B pad)

// ===================== helpers ==============================================
__device__ __forceinline__ float lrelu(float x) { return fmaxf(x, 0.1f * x); }

__device__ __forceinline__ uint32_t packh2(float a, float b) {
    __half2 h = __floats2half2_rn(a, b);
    return *(uint32_t*)&h;
}

// mma.sync m16n8k16 fp16 -> f32 accumulate (baseline PTX)
__device__ __forceinline__ void mmah(float c[4], const uint32_t a[4],
                                     uint32_t b0, uint32_t b1) {
    asm volatile(
        "mma.sync.aligned.m16n8k16.row.col.f32.f16.f16.f32 "
        "{%0,%1,%2,%3}, {%4,%5,%6,%7}, {%8,%9}, {%0,%1,%2,%3};"
        : "+f"(c[0]), "+f"(c[1]), "+f"(c[2]), "+f"(c[3])
        : "r"(a[0]), "r"(a[1]), "r"(a[2]), "r"(a[3]), "r"(b0), "r"(b1));
}

// ===================== prep: Wr/Wuv fp16 + pair W4 fragments ================
__global__ void prep_kernel(const float* __restrict__ cw0,
                            const float* __restrict__ cw1,
                            const float* __restrict__ cw2,
                            const float* __restrict__ cw3,
                            const float* __restrict__ mw0,
                            const float* __restrict__ mw1,
                            const float* __restrict__ mw2,
                            const float* __restrict__ mw3) {
    int idx = blockIdx.x * 256 + threadIdx.x;
    if (idx < NW) {
        int col = idx >> 9;          // n: 0..1023
        int e = idx & 511;           // k
        int p = col >> 6;
        int c = col & 63;
        const float* w; int k, t;
        if (p < 1)      { w = cw0; k = 1; t = p; }
        else if (p < 4) { w = cw1; k = 3; t = p - 1; }
        else if (p < 9) { w = cw2; k = 5; t = p - 4; }
        else            { w = cw3; k = 7; t = p - 9; }
        g_Wrh[idx] = __float2half_rn(w[(c * k + t) * EE + e]);
    } else if (idx < NW + NU) {
        int j = idx - NW;
        int n = j >> 8;              // 0..127
        int k = j & 255;
        float v;
        if (n < 64) v = mw0[n * 512 + k];
        else        v = mw0[(n - 64) * 512 + 256 + k];
        g_Wuvh[j] = __float2half_rn(v);
    } else if (idx < NW + NU + 3072) {
        int e = idx - NW - NU;
        int t4i = e & 3;
        int n = (e >> 2) & 63;       // n = nt*8 + g
        int kc = (e >> 8) & 3;
        int l = e >> 10;
        int nt = n >> 3, g = n & 7;
        const float* wsrc = (l == 0) ? mw1 : (l == 1) ? mw2 : mw3;
        int k0 = kc * 16 + 2 * t4i;
        float2 v01 = *(const float2*)(wsrc + n * 64 + k0);
        float2 v89 = *(const float2*)(wsrc + n * 64 + k0 + 8);
        uint2 pk;
        pk.x = packh2(v01.x, v01.y);
        pk.y = packh2(v89.x, v89.y);
        int e2 = (l * 4 + kc) * 32 + g * 4 + t4i;
        g_W4[e2 * 10 + nt] = pk;
    }
}

// ===================== conv GEMM: x(f32, inline cvt) @ Wr -> G(fp16) ========
#define TSG 72            // padded k-stride in fp16 units

__global__ void __launch_bounds__(256, 1)
gemm_conv_kernel(const float* __restrict__ X,
                 const __half* __restrict__ Bg,
                 __half* __restrict__ Gh) {
    const int N = GCOLS, K = EE;
    constexpr int SA = 0;
    constexpr int SB = 128 * TSG;

    extern __shared__ __half sm[];
    int tid = threadIdx.x, w = tid >> 5, lane = tid & 31;
    int g = lane >> 2, t4 = lane & 3;
    int m0 = blockIdx.y * 128, n0 = blockIdx.x * 128;
    int mw = (w & 3) * 32;
    int nw = (w >> 2) * 64;

    float Cc[2][8][4];
#pragma unroll
    for (int mt = 0; mt < 2; mt++)
#pragma unroll
        for (int nt = 0; nt < 8; nt++)
#pragma unroll
            for (int q = 0; q < 4; q++) Cc[mt][nt][q] = 0.f;

    for (int k0 = 0; k0 < K; k0 += 64) {
        float4 af[8];
        uint4 bv[4];
#pragma unroll
        for (int it = 0; it < 8; it++) {
            int u = tid + it * 256;
            int row = u >> 4;
            int kq = (u & 15) * 4;
            af[it] = *(const float4*)(X + (m0 + row) * K + k0 + kq);
        }
#pragma unroll
        for (int it = 0; it < 4; it++) {
            int u = tid + it * 256;
            int row = u >> 3;
            int kq = (u & 7) * 8;
            bv[it] = *(const uint4*)(Bg + (n0 + row) * K + k0 + kq);
        }
        __syncthreads();
#pragma unroll
        for (int it = 0; it < 8; it++) {
            int u = tid + it * 256;
            int row = u >> 4;
            int kq = (u & 15) * 4;
            uint2 hw;
            hw.x = packh2(af[it].x, af[it].y);
            hw.y = packh2(af[it].z, af[it].w);
            *(uint2*)&sm[SA + row * TSG + kq] = hw;
        }
#pragma unroll
        for (int it = 0; it < 4; it++) {
            int u = tid + it * 256;
            int row = u >> 3;
            int kq = (u & 7) * 8;
            *(uint4*)&sm[SB + row * TSG + kq] = bv[it];
        }
        __syncthreads();

#pragma unroll
        for (int kc = 0; kc < 4; kc++) {
            int kk = kc * 16 + 2 * t4;
            uint32_t A[2][4];
#pragma unroll
            for (int mt = 0; mt < 2; mt++) {
                int r0 = mw + mt * 16 + g;
                int r1 = r0 + 8;
                A[mt][0] = *(const uint32_t*)&sm[SA + r0 * TSG + kk];
                A[mt][1] = *(const uint32_t*)&sm[SA + r1 * TSG + kk];
                A[mt][2] = *(const uint32_t*)&sm[SA + r0 * TSG + kk + 8];
                A[mt][3] = *(const uint32_t*)&sm[SA + r1 * TSG + kk + 8];
            }
#pragma unroll
            for (int nt = 0; nt < 8; nt++) {
                int nrow = nw + nt * 8 + g;
                uint32_t b0 = *(const uint32_t*)&sm[SB + nrow * TSG + kk];
                uint32_t b1 = *(const uint32_t*)&sm[SB + nrow * TSG + kk + 8];
                mmah(Cc[0][nt], A[0], b0, b1);
                mmah(Cc[1][nt], A[1], b0, b1);
            }
        }
    }

#pragma unroll
    for (int mt = 0; mt < 2; mt++) {
        int r0 = m0 + mw + mt * 16 + g;
        int r1 = r0 + 8;
#pragma unroll
        for (int nt = 0; nt < 8; nt++) {
            int col = n0 + nw + nt * 8 + 2 * t4;
            *(uint32_t*)(Gh + r0 * N + col) = packh2(Cc[mt][nt][0], Cc[mt][nt][1]);
            *(uint32_t*)(Gh + r1 * N + col) = packh2(Cc[mt][nt][2], Cc[mt][nt][3]);
        }
    }
}
#define CONV_SMEM_BYTES (2 * 128 * TSG * 2)

// ===================== gather taps -> f (fp16 in/out, ILP 8) ================
__global__ void gather_f_kernel(const float* __restrict__ cb0,
                                const float* __restrict__ cb1,
                                const float* __restrict__ cb2,
                                const float* __restrict__ cb3) {
    int t0 = blockIdx.x * 256 + threadIdx.x;   // 0..65535
#pragma unroll
    for (int q = 0; q < 8; q++) {
        int idx = t0 + q * 65536;
        int row = idx >> 8;        // (l,b): 0..2047
        int m = idx & 255;
        int l = row >> 4, b = row & 15;
        int br = m >> 6, c = m & 63;
        int k, pad, base;
        const float* cb;
        if (br == 0)      { k = 1; base = 0; cb = cb0; }
        else if (br == 1) { k = 3; base = 1; cb = cb1; }
        else if (br == 2) { k = 5; base = 4; cb = cb2; }
        else              { k = 7; base = 9; cb = cb3; }
        pad = (k - 1) >> 1;
        float sum = cb[c];
        for (int tt = 0; tt < k; tt++) {
            int l2 = l - pad + tt;
            if ((unsigned)l2 < (unsigned)LL)
                sum += __half2float(g_Gh[(l2 * BB + b) * GCOLS + (base + tt) * 64 + c]);
        }
        g_ff[idx] = __float2half_rn(lrelu(sum));
    }
}

// ===================== uv GEMM: full-K single-phase fp16 ====================
#define TS2 264           // padded k-stride for K=256

__global__ void __launch_bounds__(256, 1)
gemm_uv_kernel(const __half* __restrict__ Ag,
               const __half* __restrict__ Bg,
               float* __restrict__ C) {
    const int N = 128, K = 256;
    constexpr int SA = 0;
    constexpr int SB = 64 * TS2;

    extern __shared__ __half sm[];
    int tid = threadIdx.x, w = tid >> 5, lane = tid & 31;
    int g = lane >> 2, t4 = lane & 3;
    int m0 = blockIdx.y * 64, n0 = blockIdx.x * 64;
    int mw = (w & 3) * 16;
    int nw = (w >> 2) * 32;

    uint4 av[8], bv[8];
#pragma unroll
    for (int it = 0; it < 8; it++) {
        int u = tid + it * 256;
        int row = u >> 5;
        int kq = (u & 31) * 8;
        av[it] = *(const uint4*)(Ag + (m0 + row) * K + kq);
        bv[it] = *(const uint4*)(Bg + (n0 + row) * K + kq);
    }
#pragma unroll
    for (int it = 0; it < 8; it++) {
        int u = tid + it * 256;
        int row = u >> 5;
        int kq = (u & 31) * 8;
        *(uint4*)&sm[SA + row * TS2 + kq] = av[it];
        *(uint4*)&sm[SB + row * TS2 + kq] = bv[it];
    }
    __syncthreads();

    float Cc[4][4];
#pragma unroll
    for (int nt = 0; nt < 4; nt++)
#pragma unroll
        for (int q = 0; q < 4; q++) Cc[nt][q] = 0.f;

#pragma unroll
    for (int kc = 0; kc < 16; kc++) {
        int kk = kc * 16 + 2 * t4;
        uint32_t A[4];
        int r0 = mw + g, r1 = r0 + 8;
        A[0] = *(const uint32_t*)&sm[SA + r0 * TS2 + kk];
        A[1] = *(const uint32_t*)&sm[SA + r1 * TS2 + kk];
        A[2] = *(const uint32_t*)&sm[SA + r0 * TS2 + kk + 8];
        A[3] = *(const uint32_t*)&sm[SA + r1 * TS2 + kk + 8];
#pragma unroll
        for (int nt = 0; nt < 4; nt++) {
            int nrow = nw + nt * 8 + g;
            uint32_t b0 = *(const uint32_t*)&sm[SB + nrow * TS2 + kk];
            uint32_t b1 = *(const uint32_t*)&sm[SB + nrow * TS2 + kk + 8];
            mmah(Cc[nt], A, b0, b1);
        }
    }

    int r0 = m0 + mw + g, r1 = r0 + 8;
#pragma unroll
    for (int nt = 0; nt < 4; nt++) {
        int col = n0 + nw + nt * 8 + 2 * t4;
        *(float2*)(C + r0 * N + col) = make_float2(Cc[nt][0], Cc[nt][1]);
        *(float2*)(C + r1 * N + col) = make_float2(Cc[nt][2], Cc[nt][3]);
    }
}
#define UV_SMEM_BYTES (2 * 64 * TS2 * 2)

// ===================== pair kernel (LDS.128 W fragments) ====================
// grid (16,16), 128 threads. V fp16 [i][72]; W4 80B-stride packed fragments.
#define PVH 72
#define P_W4   0
#define P_V    30720
#define P_U    49152
#define P_B    51200
#define P_RED  52224
#define P_SR   53248
#define P_TR   55296
#define PAIR_SMEM_BYTES 57344

__global__ void __launch_bounds__(128, 2)
pair_mma_kernel(const float* __restrict__ uv,
                const float* __restrict__ mb0, const float* __restrict__ mb1,
                const float* __restrict__ mb2, const float* __restrict__ mb3,
                const float* __restrict__ lw0, const float* __restrict__ lb0,
                const float* __restrict__ lw1, const float* __restrict__ lb1,
                float* __restrict__ out) {
    extern __shared__ char smp[];
    int tid = threadIdx.x, w = tid >> 5, lane = tid & 31;
    int g = lane >> 2, t4 = lane & 3;
    int b = blockIdx.y, j0 = blockIdx.x * 8;

    // ---- stage prepacked W4 fragments (flat uint4 copy: 1920 uint4) ----
    {
        uint4* dst = (uint4*)(smp + P_W4);
        const uint4* src = (const uint4*)g_W4;
#pragma unroll
        for (int q = 0; q < 15; q++)
            dst[tid + 128 * q] = src[tid + 128 * q];
    }
    // ---- stage V as fp16 [i][PVH]: thread = row i ----
    {
        __half* Vh = (__half*)(smp + P_V);
        const float* vp = uv + (tid * BB + b) * 128 + 64;
#pragma unroll
        for (int q = 0; q < 16; q++) {
            float4 v4 = *(const float4*)(vp + q * 4);
            uint2 hw;
            hw.x = packh2(v4.x, v4.y);
            hw.y = packh2(v4.z, v4.w);
            *(uint2*)&Vh[tid * PVH + q * 4] = hw;
        }
    }
    if (tid < 64) {
        float* U = (float*)(smp + P_U);
#pragma unroll
        for (int jt = 0; jt < 8; jt++)
            U[jt * 64 + tid] = uv[((j0 + jt) * BB + b) * 128 + tid];
        float* Bs = (float*)(smp + P_B);
        Bs[tid] = mb0[tid];
        Bs[64 + tid] = mb1[tid];
        Bs[128 + tid] = mb2[tid];
        Bs[192 + tid] = mb3[tid];
    }
    __syncthreads();

    const __half* Vh = (const __half*)(smp + P_V);
    const float* U = (const float*)(smp + P_U);
    const float* BIAS = (const float*)(smp + P_B);
    const char* W4p = smp + P_W4;
    float* RED = (float*)(smp + P_RED);
    float* SR = (float*)(smp + P_SR);
    int g4t80 = (g * 4 + t4) * 80;

    for (int jt = 0; jt < 8; jt++) {
        uint32_t A[2][4][4];

        // ---- layer-1 A fragments: x = lrelu(u + v + b0) ----
#pragma unroll
        for (int kc = 0; kc < 4; kc++) {
            int k0 = kc * 16 + 2 * t4;
            float2 u01 = *(const float2*)&U[jt * 64 + k0];
            float2 u89 = *(const float2*)&U[jt * 64 + k0 + 8];
            float2 b01 = *(const float2*)&BIAS[k0];
            float2 b89 = *(const float2*)&BIAS[k0 + 8];
            float ub0 = u01.x + b01.x, ub1 = u01.y + b01.y;
            float ub8 = u89.x + b89.x, ub9 = u89.y + b89.y;
#pragma unroll
            for (int mt = 0; mt < 2; mt++) {
                int r0 = w * 32 + mt * 16 + g;
                int r1 = r0 + 8;
                float2 fa0 = __half22float2(*(const __half2*)&Vh[r0 * PVH + k0]);
                float2 fa8 = __half22float2(*(const __half2*)&Vh[r0 * PVH + k0 + 8]);
                float2 fb0 = __half22float2(*(const __half2*)&Vh[r1 * PVH + k0]);
                float2 fb8 = __half22float2(*(const __half2*)&Vh[r1 * PVH + k0 + 8]);
                A[mt][kc][0] = packh2(lrelu(ub0 + fa0.x), lrelu(ub1 + fa0.y));
                A[mt][kc][1] = packh2(lrelu(ub0 + fb0.x), lrelu(ub1 + fb0.y));
                A[mt][kc][2] = packh2(lrelu(ub8 + fa8.x), lrelu(ub9 + fa8.y));
                A[mt][kc][3] = packh2(lrelu(ub8 + fb8.x), lrelu(ub9 + fb8.y));
            }
        }

        // ---- 3 chained MMA layers (single-term: A*W, LDS.128 frags) ----
        float Cc[2][8][4];
#pragma unroll
        for (int l = 0; l < 3; l++) {
#pragma unroll
            for (int mt = 0; mt < 2; mt++)
#pragma unroll
                for (int nt = 0; nt < 8; nt++)
#pragma unroll
                    for (int q = 0; q < 4; q++) Cc[mt][nt][q] = 0.f;

#pragma unroll
            for (int kc = 0; kc < 4; kc++) {
                const char* wb = W4p + (l * 4 + kc) * 32 * 80 + g4t80;
#pragma unroll
                for (int ntp = 0; ntp < 4; ntp++) {
                    uint4 wq = *(const uint4*)(wb + ntp * 16);
                    mmah(Cc[0][2 * ntp],     A[0][kc], wq.x, wq.y);
                    mmah(Cc[1][2 * ntp],     A[1][kc], wq.x, wq.y);
                    mmah(Cc[0][2 * ntp + 1], A[0][kc], wq.z, wq.w);
                    mmah(Cc[1][2 * ntp + 1], A[1][kc], wq.z, wq.w);
                }
            }

            if (l < 2) {
                const float* bl = BIAS + 64 * (l + 1);
#pragma unroll
                for (int nt = 0; nt < 8; nt++) {
                    int col = nt * 8 + 2 * t4;
                    float bx = bl[col], by = bl[col + 1];
                    int kc2 = nt >> 1, ri = (nt & 1) * 2;
#pragma unroll
                    for (int mt = 0; mt < 2; mt++) {
                        float h0 = lrelu(Cc[mt][nt][0] + bx);
                        float h1 = lrelu(Cc[mt][nt][1] + by);
                        float h2 = lrelu(Cc[mt][nt][2] + bx);
                        float h3 = lrelu(Cc[mt][nt][3] + by);
                        A[mt][kc2][ri]     = packh2(h0, h1);
                        A[mt][kc2][ri + 1] = packh2(h2, h3);
                    }
                }
            }
        }

        // ---- final: bias + lrelu, reduce over i ----
        {
            const float* bl = BIAS + 192;
#pragma unroll
            for (int nt = 0; nt < 8; nt++) {
                int col = nt * 8 + 2 * t4;
                float bx = bl[col], by = bl[col + 1];
                float s0 = lrelu(Cc[0][nt][0] + bx) + lrelu(Cc[0][nt][2] + bx) +
                           lrelu(Cc[1][nt][0] + bx) + lrelu(Cc[1][nt][2] + bx);
                float s1 = lrelu(Cc[0][nt][1] + by) + lrelu(Cc[0][nt][3] + by) +
                           lrelu(Cc[1][nt][1] + by) + lrelu(Cc[1][nt][3] + by);
                s0 += __shfl_xor_sync(0xffffffffu, s0, 4);
                s0 += __shfl_xor_sync(0xffffffffu, s0, 8);
                s0 += __shfl_xor_sync(0xffffffffu, s0, 16);
                s1 += __shfl_xor_sync(0xffffffffu, s1, 4);
                s1 += __shfl_xor_sync(0xffffffffu, s1, 8);
                s1 += __shfl_xor_sync(0xffffffffu, s1, 16);
                if (lane < 4) {
                    RED[w * 64 + col] = s0;
                    RED[w * 64 + col + 1] = s1;
                }
            }
        }
        __syncthreads();
        if (tid < 64) {
            float s = RED[tid] + RED[64 + tid] + RED[128 + tid] + RED[192 + tid];
            SR[jt * 64 + tid] = s;
        }
        __syncthreads();
    }

    // ---- fused head: t = lrelu(s@lw0.T+lb0); out = lrelu(t@lw1.T+lb1) ----
    float* TR = (float*)(smp + P_TR);
#pragma unroll
    for (int q = 0; q < 4; q++) {
        int idx = tid + 128 * q;
        int jt = idx >> 6, o = idx & 63;
        const float* wr = lw0 + o * 64;
        float acc = lb0[o];
#pragma unroll
        for (int c = 0; c < 64; c += 4) {
            float4 w4 = *(const float4*)(wr + c);
            acc += SR[jt * 64 + c] * w4.x + SR[jt * 64 + c + 1] * w4.y +
                   SR[jt * 64 + c + 2] * w4.z + SR[jt * 64 + c + 3] * w4.w;
        }
        TR[idx] = lrelu(acc);
    }
    __syncthreads();
#pragma unroll
    for (int q = 0; q < 16; q++) {
        int idx = tid + 128 * q;
        int jt = idx >> 8, o = idx & 255;
        const float* wr = lw1 + o * 64;
        float acc = lb1[o];
#pragma unroll
        for (int c = 0; c < 64; c += 4) {
            float4 w4 = *(const float4*)(wr + c);
            acc += TR[jt * 64 + c] * w4.x + TR[jt * 64 + c + 1] * w4.y +
                   TR[jt * 64 + c + 2] * w4.z + TR[jt * 64 + c + 3] * w4.w;
        }
        out[((j0 + jt) * BB + b) * 256 + o] = lrelu(acc);
    }
}

// ===================== host launch ==========================================
extern "C" void kernel_launch(void* const* d_in, const int* in_sizes, int n_in,
                              void* d_out, int out_size) {
    const float* x   = (const float*)d_in[0];
    const float* cw0 = (const float*)d_in[1];
    const float* cb0 = (const float*)d_in[2];
    const float* cw1 = (const float*)d_in[3];
    const float* cb1 = (const float*)d_in[4];
    const float* cw2 = (const float*)d_in[5];
    const float* cb2 = (const float*)d_in[6];
    const float* cw3 = (const float*)d_in[7];
    const float* cb3 = (const float*)d_in[8];
    const float* mw0 = (const float*)d_in[9];
    const float* mb0 = (const float*)d_in[10];
    const float* mw1 = (const float*)d_in[11];
    const float* mb1 = (const float*)d_in[12];
    const float* mw2 = (const float*)d_in[13];
    const float* mb2 = (const float*)d_in[14];
    const float* mw3 = (const float*)d_in[15];
    const float* mb3 = (const float*)d_in[16];
    const float* lw0 = (const float*)d_in[17];
    const float* lb0 = (const float*)d_in[18];
    const float* lw1 = (const float*)d_in[19];
    const float* lb1 = (const float*)d_in[20];
    float* out = (float*)d_out;

    float* uvb;
    __half *Gh, *ff, *Wrh, *Wuvh;
    cudaGetSymbolAddress((void**)&Gh, g_Gh);
    cudaGetSymbolAddress((void**)&uvb, g_uv);
    cudaGetSymbolAddress((void**)&ff, g_ff);
    cudaGetSymbolAddress((void**)&Wrh, g_Wrh);
    cudaGetSymbolAddress((void**)&Wuvh, g_Wuvh);

    // 1) prep (weights + pair W4 fragments)
    prep_kernel<<<(NW + NU + 3072 + 255) / 256, 256>>>(
        cw0, cw1, cw2, cw3, mw0, mw1, mw2, mw3);

    // 2) conv as GEMM: G = x @ Wr (x cvt inline, G fp16)
    cudaFuncSetAttribute(gemm_conv_kernel,
                         cudaFuncAttributeMaxDynamicSharedMemorySize,
                         CONV_SMEM_BYTES);
    gemm_conv_kernel<<<dim3(GCOLS / 128, ROWS / 128), 256, CONV_SMEM_BYTES>>>(
        x, Wrh, Gh);

    // 3) gather taps -> f (fp16)
    gather_f_kernel<<<256, 256>>>(cb0, cb1, cb2, cb3);

    // 4) uv = f @ Wuv (full-K single-phase, 64x64 tiles)
    cudaFuncSetAttribute(gemm_uv_kernel,
                         cudaFuncAttributeMaxDynamicSharedMemorySize,
                         UV_SMEM_BYTES);
    gemm_uv_kernel<<<dim3(2, ROWS / 64), 256, UV_SMEM_BYTES>>>(
        ff, Wuvh, uvb);

    // 5) pair stage + fused head
    cudaFuncSetAttribute(pair_mma_kernel,
                         cudaFuncAttributeMaxDynamicSharedMemorySize,
                         PAIR_SMEM_BYTES);
    pair_mma_kernel<<<dim3(16, 16), 128, PAIR_SMEM_BYTES>>>(
        uvb, mb0, mb1, mb2, mb3, lw0, lb0, lw1, lb1, out);
}